// round 4
// baseline (speedup 1.0000x reference)
#include <cuda_runtime.h>
#include <cuda_bf16.h>
#include <cstdint>

#define D     128
#define NMAX  50000
#define EMAX  600000
#define EPS   1e-8f

#define SWB32 68            // A/W smem row stride in b32 units (136 bf16 = 272B)
#define ROWB  272           // bytes per bf16 tile row
#define SWF   132           // f32 staging stride

// ---------------- scratch (static device globals) ----------------
__device__ float g_y[NMAX * D];
__device__ int   g_hist[NMAX];     // in-degree
__device__ int   g_off[NMAX];      // CSR row offsets (exclusive)
__device__ int   g_woff[NMAX];     // working copy for fill
__device__ int   g_csr[EMAX];      // src indices grouped by dst
// transposed + split weights: [mat][n][k] bf16; mat: 0=msg1,1=msg2,2=upd1,3=upd2
__device__ __nv_bfloat16 g_wth[4 * D * D];
__device__ __nv_bfloat16 g_wtl[4 * D * D];

// ---------------- smem layout (bytes) ----------------
#define OFF_AH 0u
#define OFF_AL 34816u
#define OFF_WH 69632u
#define OFF_WL 104448u
#define OFF_B1 139264u
#define OFF_B2 139776u
#define SMEM_DYN 140288u

// ---------------- mma.sync helper (bf16, fp32 accum) ----------------
__device__ __forceinline__ void mma16816(float* c, const uint32_t* a,
                                         uint32_t b0, uint32_t b1) {
    asm volatile(
        "mma.sync.aligned.m16n8k16.row.col.f32.bf16.bf16.f32 "
        "{%0,%1,%2,%3}, {%4,%5,%6,%7}, {%8,%9}, {%0,%1,%2,%3};"
        : "+f"(c[0]), "+f"(c[1]), "+f"(c[2]), "+f"(c[3])
        : "r"(a[0]), "r"(a[1]), "r"(a[2]), "r"(a[3]), "r"(b0), "r"(b1));
}

// 3-term split GEMM: acc += (Ah+Al) @ (Wh+Wl)^T  (dropping Al*Wl)
__device__ __forceinline__ void do_gemm(
    const uint32_t* __restrict__ Ah32, const uint32_t* __restrict__ Al32,
    const uint32_t* __restrict__ Wh32, const uint32_t* __restrict__ Wl32,
    int wm, int wn, int gid, int tig, float acc[2][8][4])
{
    #pragma unroll 2
    for (int ks = 0; ks < 8; ks++) {
        uint32_t ah[2][4], al[2][4];
        #pragma unroll
        for (int ms = 0; ms < 2; ms++) {
            int r = wm * 32 + ms * 16 + gid;
            const uint32_t* p = Ah32 + r * SWB32 + ks * 8 + tig;
            ah[ms][0] = p[0]; ah[ms][1] = p[8 * SWB32];
            ah[ms][2] = p[4]; ah[ms][3] = p[8 * SWB32 + 4];
            const uint32_t* q = Al32 + r * SWB32 + ks * 8 + tig;
            al[ms][0] = q[0]; al[ms][1] = q[8 * SWB32];
            al[ms][2] = q[4]; al[ms][3] = q[8 * SWB32 + 4];
        }
        #pragma unroll
        for (int ns = 0; ns < 8; ns++) {
            int nr = wn * 64 + ns * 8 + gid;
            const uint32_t* bp = Wh32 + nr * SWB32 + ks * 8 + tig;
            uint32_t bh0 = bp[0], bh1 = bp[4];
            const uint32_t* bq = Wl32 + nr * SWB32 + ks * 8 + tig;
            uint32_t bl0 = bq[0], bl1 = bq[4];
            #pragma unroll
            for (int ms = 0; ms < 2; ms++) {
                mma16816(acc[ms][ns], ah[ms], bh0, bh1);
                mma16816(acc[ms][ns], ah[ms], bl0, bl1);
                mma16816(acc[ms][ns], al[ms], bh0, bh1);
            }
        }
    }
}

// ---------------- CSR build kernels ----------------
__global__ void zero_hist_kernel(int n) {
    int i = blockIdx.x * blockDim.x + threadIdx.x;
    if (i < n) g_hist[i] = 0;
}

__global__ void hist_kernel(const int* __restrict__ ei, int E) {
    int e = blockIdx.x * blockDim.x + threadIdx.x;
    if (e < E) atomicAdd(&g_hist[ei[e]], 1);
}

// single-block exclusive scan over g_hist -> g_off (and copy to g_woff)
__global__ __launch_bounds__(1024, 1) void scan_kernel(int N) {
    __shared__ int ssum[1024];
    int t = threadIdx.x;
    int CH = (N + 1023) / 1024;
    int base = t * CH;
    int s = 0;
    for (int i = 0; i < CH; i++) {
        int idx = base + i;
        if (idx < N) s += g_hist[idx];
    }
    ssum[t] = s;
    __syncthreads();
    #pragma unroll
    for (int d = 1; d < 1024; d <<= 1) {
        int v = (t >= d) ? ssum[t - d] : 0;
        __syncthreads();
        ssum[t] += v;
        __syncthreads();
    }
    int run = (t == 0) ? 0 : ssum[t - 1];
    for (int i = 0; i < CH; i++) {
        int idx = base + i;
        if (idx < N) {
            g_off[idx]  = run;
            g_woff[idx] = run;
            run += g_hist[idx];
        }
    }
}

__global__ void fill_kernel(const int* __restrict__ ei, int E) {
    int e = blockIdx.x * blockDim.x + threadIdx.x;
    if (e < E) {
        int dst = ei[e];
        int src = ei[E + e];
        int pos = atomicAdd(&g_woff[dst], 1);
        g_csr[pos] = src;
    }
}

// transpose + bf16 hi/lo split of the 4 weight matrices
__global__ void prep_w_kernel(const float* __restrict__ w0, const float* __restrict__ w1,
                              const float* __restrict__ w2, const float* __restrict__ w3) {
    int g = blockIdx.x * blockDim.x + threadIdx.x;    // 0..16383
    int mat = g >> 12;
    int rem = g & 4095;
    int k = rem >> 5;
    int n4 = rem & 31;
    const float* W = (mat == 0) ? w0 : (mat == 1) ? w1 : (mat == 2) ? w2 : w3;
    float4 v = ((const float4*)W)[k * 32 + n4];
    float a[4] = {v.x, v.y, v.z, v.w};
    #pragma unroll
    for (int j = 0; j < 4; j++) {
        int n = n4 * 4 + j;
        float f = a[j];
        __nv_bfloat16 hi = __float2bfloat16_rn(f);
        __nv_bfloat16 lo = __float2bfloat16_rn(f - __bfloat162float(hi));
        g_wth[mat * D * D + n * D + k] = hi;
        g_wtl[mat * D * D + n * D + k] = lo;
    }
}

__device__ __forceinline__ void f4add(float4& a, const float4 b) {
    a.x += b.x; a.y += b.y; a.z += b.z; a.w += b.w;
}

// ---------------- fused MLP via mma.sync (HMMA) ----------------
// mode 0: g_y = MLP1(logmap0(x))
// mode 1: out = expmap0(MLP2(mean_{CSR} g_y[src]))
__global__ __launch_bounds__(256, 1) void mlp_tc_kernel(
    const float* __restrict__ xin,
    const float* __restrict__ B1v, const float* __restrict__ B2v,
    float* __restrict__ outp, int N, int mode)
{
    extern __shared__ char sb[];
    uint32_t* Ah32 = (uint32_t*)(sb + OFF_AH);
    uint32_t* Al32 = (uint32_t*)(sb + OFF_AL);
    uint32_t* Wh32 = (uint32_t*)(sb + OFF_WH);
    uint32_t* Wl32 = (uint32_t*)(sb + OFF_WL);
    float* B1s = (float*)(sb + OFF_B1);
    float* B2s = (float*)(sb + OFF_B2);

    const int tid  = threadIdx.x;
    const int wid  = tid >> 5;
    const int lane = tid & 31;
    const int gid  = lane >> 2;
    const int tig  = lane & 3;
    const int wm   = wid & 3;
    const int wn   = wid >> 2;
    const int row0 = blockIdx.x * 128;

    if (tid < 128) B1s[tid] = B1v[tid];
    else           B2s[tid - 128] = B2v[tid - 128];

    // ---- load W1 hi/lo into smem ----
    {
        int m1 = mode * 2;
        const float4* sh = (const float4*)(g_wth + m1 * D * D);
        const float4* sl = (const float4*)(g_wtl + m1 * D * D);
        #pragma unroll
        for (int it = 0; it < 8; it++) {
            int idx = tid + it * 256;
            int n = idx >> 4, c = idx & 15;
            *(float4*)(sb + OFF_WH + n * ROWB + c * 16) = sh[idx];
            *(float4*)(sb + OFF_WL + n * ROWB + c * 16) = sl[idx];
        }
    }

    // ---- input rows: logmap0(x) (mode 0) or CSR-gather mean (mode 1) ----
    {
        const float4* x4 = (const float4*)xin;
        const float4* y4 = (const float4*)g_y;
        for (int i = 0; i < 16; i++) {
            int r = wid * 16 + i;
            int rg = row0 + r;
            float4 v = make_float4(0.f, 0.f, 0.f, 0.f);
            if (rg < N) {
                if (mode == 0) {
                    v = x4[rg * 32 + lane];
                    float ss = v.x * v.x + v.y * v.y + v.z * v.z + v.w * v.w;
                    #pragma unroll
                    for (int m = 16; m >= 1; m >>= 1) ss += __shfl_xor_sync(0xffffffffu, ss, m);
                    float nrm = sqrtf(ss);
                    float nc  = fminf(fmaxf(nrm, EPS), 1.0f - 1e-5f);
                    float f   = atanhf(nc) / nc;
                    v.x *= f; v.y *= f; v.z *= f; v.w *= f;
                } else {
                    int start = g_off[rg];
                    int deg   = g_hist[rg];
                    float4 v1 = make_float4(0.f, 0.f, 0.f, 0.f);
                    float4 v2 = make_float4(0.f, 0.f, 0.f, 0.f);
                    float4 v3 = make_float4(0.f, 0.f, 0.f, 0.f);
                    int j = 0;
                    for (; j + 4 <= deg; j += 4) {
                        int s0 = g_csr[start + j];
                        int s1 = g_csr[start + j + 1];
                        int s2 = g_csr[start + j + 2];
                        int s3 = g_csr[start + j + 3];
                        f4add(v,  y4[s0 * 32 + lane]);
                        f4add(v1, y4[s1 * 32 + lane]);
                        f4add(v2, y4[s2 * 32 + lane]);
                        f4add(v3, y4[s3 * 32 + lane]);
                    }
                    for (; j < deg; j++)
                        f4add(v, y4[g_csr[start + j] * 32 + lane]);
                    f4add(v1, v2); f4add(v, v3); f4add(v, v1);
                    float inv = 1.0f / ((float)deg + EPS);
                    v.x *= inv; v.y *= inv; v.z *= inv; v.w *= inv;
                }
            }
            __nv_bfloat16 h0 = __float2bfloat16_rn(v.x), h1 = __float2bfloat16_rn(v.y);
            __nv_bfloat16 h2 = __float2bfloat16_rn(v.z), h3 = __float2bfloat16_rn(v.w);
            __nv_bfloat162 hp0(h0, h1), hp1(h2, h3);
            __nv_bfloat162 lp0(__float2bfloat16_rn(v.x - __bfloat162float(h0)),
                               __float2bfloat16_rn(v.y - __bfloat162float(h1)));
            __nv_bfloat162 lp1(__float2bfloat16_rn(v.z - __bfloat162float(h2)),
                               __float2bfloat16_rn(v.w - __bfloat162float(h3)));
            *(uint2*)(sb + OFF_AH + r * ROWB + lane * 8) =
                make_uint2(*(uint32_t*)&hp0, *(uint32_t*)&hp1);
            *(uint2*)(sb + OFF_AL + r * ROWB + lane * 8) =
                make_uint2(*(uint32_t*)&lp0, *(uint32_t*)&lp1);
        }
    }
    __syncthreads();

    float acc[2][8][4];

    // ---- GEMM1 ----
    #pragma unroll
    for (int ms = 0; ms < 2; ms++)
        #pragma unroll
        for (int ns = 0; ns < 8; ns++)
            #pragma unroll
            for (int j = 0; j < 4; j++) acc[ms][ns][j] = 0.f;
    do_gemm(Ah32, Al32, Wh32, Wl32, wm, wn, gid, tig, acc);
    __syncthreads();

    // ---- epilogue1: T = relu(acc + B1) -> Ah/Al ----
    #pragma unroll
    for (int ms = 0; ms < 2; ms++) {
        int r = wm * 32 + ms * 16 + gid;
        #pragma unroll
        for (int ns = 0; ns < 8; ns++) {
            int col = wn * 64 + ns * 8 + tig * 2;
            float b0 = B1s[col], b1 = B1s[col + 1];
            float v0 = fmaxf(acc[ms][ns][0] + b0, 0.f);
            float v1 = fmaxf(acc[ms][ns][1] + b1, 0.f);
            float v2 = fmaxf(acc[ms][ns][2] + b0, 0.f);
            float v3 = fmaxf(acc[ms][ns][3] + b1, 0.f);
            __nv_bfloat16 a0 = __float2bfloat16_rn(v0), a1 = __float2bfloat16_rn(v1);
            __nv_bfloat16 a2 = __float2bfloat16_rn(v2), a3 = __float2bfloat16_rn(v3);
            __nv_bfloat162 hA(a0, a1), hB(a2, a3);
            __nv_bfloat162 lA(__float2bfloat16_rn(v0 - __bfloat162float(a0)),
                              __float2bfloat16_rn(v1 - __bfloat162float(a1)));
            __nv_bfloat162 lB(__float2bfloat16_rn(v2 - __bfloat162float(a2)),
                              __float2bfloat16_rn(v3 - __bfloat162float(a3)));
            *(uint32_t*)(sb + OFF_AH + r * ROWB + col * 2)       = *(uint32_t*)&hA;
            *(uint32_t*)(sb + OFF_AL + r * ROWB + col * 2)       = *(uint32_t*)&lA;
            *(uint32_t*)(sb + OFF_AH + (r + 8) * ROWB + col * 2) = *(uint32_t*)&hB;
            *(uint32_t*)(sb + OFF_AL + (r + 8) * ROWB + col * 2) = *(uint32_t*)&lB;
        }
    }

    // ---- load W2 hi/lo ----
    {
        int m2 = mode * 2 + 1;
        const float4* sh = (const float4*)(g_wth + m2 * D * D);
        const float4* sl = (const float4*)(g_wtl + m2 * D * D);
        #pragma unroll
        for (int it = 0; it < 8; it++) {
            int idx = tid + it * 256;
            int n = idx >> 4, c = idx & 15;
            *(float4*)(sb + OFF_WH + n * ROWB + c * 16) = sh[idx];
            *(float4*)(sb + OFF_WL + n * ROWB + c * 16) = sl[idx];
        }
    }
    __syncthreads();

    // ---- GEMM2 ----
    #pragma unroll
    for (int ms = 0; ms < 2; ms++)
        #pragma unroll
        for (int ns = 0; ns < 8; ns++)
            #pragma unroll
            for (int j = 0; j < 4; j++) acc[ms][ns][j] = 0.f;
    do_gemm(Ah32, Al32, Wh32, Wl32, wm, wn, gid, tig, acc);

    if (mode == 0) {
        #pragma unroll
        for (int ms = 0; ms < 2; ms++) {
            int r = wm * 32 + ms * 16 + gid;
            #pragma unroll
            for (int ns = 0; ns < 8; ns++) {
                int col = wn * 64 + ns * 8 + tig * 2;
                float b0 = B2s[col], b1 = B2s[col + 1];
                int rg = row0 + r;
                if (rg < N)
                    *(float2*)(g_y + rg * D + col) =
                        make_float2(acc[ms][ns][0] + b0, acc[ms][ns][1] + b1);
                if (rg + 8 < N)
                    *(float2*)(g_y + (rg + 8) * D + col) =
                        make_float2(acc[ms][ns][2] + b0, acc[ms][ns][3] + b1);
            }
        }
    } else {
        __syncthreads();
        float* Sf = (float*)(sb + OFF_WH);
        #pragma unroll
        for (int ms = 0; ms < 2; ms++) {
            int r = wm * 32 + ms * 16 + gid;
            #pragma unroll
            for (int ns = 0; ns < 8; ns++) {
                int col = wn * 64 + ns * 8 + tig * 2;
                float b0 = B2s[col], b1 = B2s[col + 1];
                *(float2*)(Sf + r * SWF + col) =
                    make_float2(acc[ms][ns][0] + b0, acc[ms][ns][1] + b1);
                *(float2*)(Sf + (r + 8) * SWF + col) =
                    make_float2(acc[ms][ns][2] + b0, acc[ms][ns][3] + b1);
            }
        }
        __syncthreads();
        int r = tid >> 1, h = tid & 1;
        float ss = 0.f;
        float4 vv[16];
        #pragma unroll
        for (int j = 0; j < 16; j++) {
            float4 v = *(float4*)(Sf + r * SWF + h * 64 + j * 4);
            vv[j] = v;
            ss += v.x * v.x + v.y * v.y + v.z * v.z + v.w * v.w;
        }
        ss += __shfl_xor_sync(0xffffffffu, ss, 1);
        float nrm = sqrtf(ss);
        float nc  = fmaxf(nrm, EPS);
        float fm  = tanhf(nc) / nc;
        int rg = row0 + r;
        if (rg < N) {
            #pragma unroll
            for (int j = 0; j < 16; j++) {
                float4 v = vv[j];
                v.x *= fm; v.y *= fm; v.z *= fm; v.w *= fm;
                ((float4*)outp)[rg * 32 + h * 16 + j] = v;
            }
        }
    }
}

// ---------------- launch ----------------
extern "C" void kernel_launch(void* const* d_in, const int* in_sizes, int n_in,
                              void* d_out, int out_size) {
    const float* x      = (const float*)d_in[0];
    const int*   ei     = (const int*)d_in[1];
    const float* w_msg1 = (const float*)d_in[2];
    const float* b_msg1 = (const float*)d_in[3];
    const float* w_msg2 = (const float*)d_in[4];
    const float* b_msg2 = (const float*)d_in[5];
    const float* w_upd1 = (const float*)d_in[6];
    const float* b_upd1 = (const float*)d_in[7];
    const float* w_upd2 = (const float*)d_in[8];
    const float* b_upd2 = (const float*)d_in[9];
    float* out = (float*)d_out;

    int N = in_sizes[0] / D;
    int E = in_sizes[1] / 2;

    cudaFuncSetAttribute(mlp_tc_kernel,
                         cudaFuncAttributeMaxDynamicSharedMemorySize, SMEM_DYN);

    prep_w_kernel<<<64, 256>>>(w_msg1, w_msg2, w_upd1, w_upd2);
    zero_hist_kernel<<<(N + 255) / 256, 256>>>(N);
    hist_kernel<<<(E + 255) / 256, 256>>>(ei, E);
    scan_kernel<<<1, 1024>>>(N);
    fill_kernel<<<(E + 255) / 256, 256>>>(ei, E);

    int mblocks = (N + 127) / 128;
    mlp_tc_kernel<<<mblocks, 256, SMEM_DYN>>>(x, b_msg1, b_msg2, nullptr, N, 0);
    mlp_tc_kernel<<<mblocks, 256, SMEM_DYN>>>(nullptr, b_upd1, b_upd2, out, N, 1);
}

// round 5
// speedup vs baseline: 1.3908x; 1.3908x over previous
#include <cuda_runtime.h>
#include <cuda_bf16.h>
#include <cstdint>

#define D      128
#define NMAX   50000
#define DEGMAX 128
#define EPS    1e-8f

#define SWB32 68            // A/W smem row stride in b32 units (136 bf16 = 272B)
#define ROWB  272           // bytes per bf16 tile row
#define SWF   132           // f32 staging stride

// ---------------- scratch (static device globals) ----------------
__device__ float g_y[NMAX * D];
__device__ int   g_hist[NMAX];              // in-degree (atomic counters)
__device__ int   g_csr[NMAX * DEGMAX];      // padded neighbor buckets
// transposed + split weights: [mat][n][k] bf16; mat: 0=msg1,1=msg2,2=upd1,3=upd2
__device__ __nv_bfloat16 g_wth[4 * D * D];
__device__ __nv_bfloat16 g_wtl[4 * D * D];

// ---------------- smem layout (bytes) ----------------
#define OFF_AH 0u
#define OFF_AL 34816u
#define OFF_WH 69632u
#define OFF_WL 104448u
#define OFF_B1 139264u
#define OFF_B2 139776u
#define SMEM_DYN 140288u

// ---------------- mma.sync helper (bf16, fp32 accum) ----------------
__device__ __forceinline__ void mma16816(float* c, const uint32_t* a,
                                         uint32_t b0, uint32_t b1) {
    asm volatile(
        "mma.sync.aligned.m16n8k16.row.col.f32.bf16.bf16.f32 "
        "{%0,%1,%2,%3}, {%4,%5,%6,%7}, {%8,%9}, {%0,%1,%2,%3};"
        : "+f"(c[0]), "+f"(c[1]), "+f"(c[2]), "+f"(c[3])
        : "r"(a[0]), "r"(a[1]), "r"(a[2]), "r"(a[3]), "r"(b0), "r"(b1));
}

// 3-term split GEMM: acc += (Ah+Al) @ (Wh+Wl)^T  (dropping Al*Wl)
__device__ __forceinline__ void do_gemm(
    const uint32_t* __restrict__ Ah32, const uint32_t* __restrict__ Al32,
    const uint32_t* __restrict__ Wh32, const uint32_t* __restrict__ Wl32,
    int wm, int wn, int gid, int tig, float acc[2][8][4])
{
    #pragma unroll 2
    for (int ks = 0; ks < 8; ks++) {
        uint32_t ah[2][4], al[2][4];
        #pragma unroll
        for (int ms = 0; ms < 2; ms++) {
            int r = wm * 32 + ms * 16 + gid;
            const uint32_t* p = Ah32 + r * SWB32 + ks * 8 + tig;
            ah[ms][0] = p[0]; ah[ms][1] = p[8 * SWB32];
            ah[ms][2] = p[4]; ah[ms][3] = p[8 * SWB32 + 4];
            const uint32_t* q = Al32 + r * SWB32 + ks * 8 + tig;
            al[ms][0] = q[0]; al[ms][1] = q[8 * SWB32];
            al[ms][2] = q[4]; al[ms][3] = q[8 * SWB32 + 4];
        }
        #pragma unroll
        for (int ns = 0; ns < 8; ns++) {
            int nr = wn * 64 + ns * 8 + gid;
            const uint32_t* bp = Wh32 + nr * SWB32 + ks * 8 + tig;
            uint32_t bh0 = bp[0], bh1 = bp[4];
            const uint32_t* bq = Wl32 + nr * SWB32 + ks * 8 + tig;
            uint32_t bl0 = bq[0], bl1 = bq[4];
            #pragma unroll
            for (int ms = 0; ms < 2; ms++) {
                mma16816(acc[ms][ns], ah[ms], bh0, bh1);
                mma16816(acc[ms][ns], ah[ms], bl0, bl1);
                mma16816(acc[ms][ns], al[ms], bh0, bh1);
            }
        }
    }
}

// ---------------- bucket-CSR build (no scan needed) ----------------
__global__ void zero_hist_kernel(int n) {
    int i = blockIdx.x * blockDim.x + threadIdx.x;
    if (i < n) g_hist[i] = 0;
}

__global__ void fill_kernel(const int* __restrict__ ei, int E) {
    int e = blockIdx.x * blockDim.x + threadIdx.x;
    if (e < E) {
        int dst = ei[e];
        int src = ei[E + e];
        int pos = atomicAdd(&g_hist[dst], 1);
        if (pos < DEGMAX) g_csr[dst * DEGMAX + pos] = src;
    }
}

// transpose + bf16 hi/lo split of the 4 weight matrices
__global__ void prep_w_kernel(const float* __restrict__ w0, const float* __restrict__ w1,
                              const float* __restrict__ w2, const float* __restrict__ w3) {
    int g = blockIdx.x * blockDim.x + threadIdx.x;    // 0..16383
    int mat = g >> 12;
    int rem = g & 4095;
    int k = rem >> 5;
    int n4 = rem & 31;
    const float* W = (mat == 0) ? w0 : (mat == 1) ? w1 : (mat == 2) ? w2 : w3;
    float4 v = ((const float4*)W)[k * 32 + n4];
    float a[4] = {v.x, v.y, v.z, v.w};
    #pragma unroll
    for (int j = 0; j < 4; j++) {
        int n = n4 * 4 + j;
        float f = a[j];
        __nv_bfloat16 hi = __float2bfloat16_rn(f);
        __nv_bfloat16 lo = __float2bfloat16_rn(f - __bfloat162float(hi));
        g_wth[mat * D * D + n * D + k] = hi;
        g_wtl[mat * D * D + n * D + k] = lo;
    }
}

__device__ __forceinline__ void f4add(float4& a, const float4 b) {
    a.x += b.x; a.y += b.y; a.z += b.z; a.w += b.w;
}

// ---------------- fused MLP via mma.sync (HMMA) ----------------
// mode 0: g_y = MLP1(logmap0(x))
// mode 1: out = expmap0(MLP2(mean_{bucket} g_y[src]))
__global__ __launch_bounds__(256, 1) void mlp_tc_kernel(
    const float* __restrict__ xin,
    const float* __restrict__ B1v, const float* __restrict__ B2v,
    float* __restrict__ outp, int N, int mode)
{
    extern __shared__ char sb[];
    uint32_t* Ah32 = (uint32_t*)(sb + OFF_AH);
    uint32_t* Al32 = (uint32_t*)(sb + OFF_AL);
    uint32_t* Wh32 = (uint32_t*)(sb + OFF_WH);
    uint32_t* Wl32 = (uint32_t*)(sb + OFF_WL);
    float* B1s = (float*)(sb + OFF_B1);
    float* B2s = (float*)(sb + OFF_B2);

    const int tid  = threadIdx.x;
    const int wid  = tid >> 5;
    const int lane = tid & 31;
    const int gid  = lane >> 2;
    const int tig  = lane & 3;
    const int wm   = wid & 3;
    const int wn   = wid >> 2;
    const int row0 = blockIdx.x * 128;

    if (tid < 128) B1s[tid] = B1v[tid];
    else           B2s[tid - 128] = B2v[tid - 128];

    // ---- load W1 hi/lo into smem ----
    {
        int m1 = mode * 2;
        const float4* sh = (const float4*)(g_wth + m1 * D * D);
        const float4* sl = (const float4*)(g_wtl + m1 * D * D);
        #pragma unroll
        for (int it = 0; it < 8; it++) {
            int idx = tid + it * 256;
            int n = idx >> 4, c = idx & 15;
            *(float4*)(sb + OFF_WH + n * ROWB + c * 16) = sh[idx];
            *(float4*)(sb + OFF_WL + n * ROWB + c * 16) = sl[idx];
        }
    }

    // ---- input rows: logmap0(x) (mode 0) or bucket-gather mean (mode 1) ----
    {
        const float4* x4 = (const float4*)xin;
        const float4* y4 = (const float4*)g_y;
        for (int i = 0; i < 16; i++) {
            int r = wid * 16 + i;
            int rg = row0 + r;
            float4 v = make_float4(0.f, 0.f, 0.f, 0.f);
            if (rg < N) {
                if (mode == 0) {
                    v = x4[rg * 32 + lane];
                    float ss = v.x * v.x + v.y * v.y + v.z * v.z + v.w * v.w;
                    #pragma unroll
                    for (int m = 16; m >= 1; m >>= 1) ss += __shfl_xor_sync(0xffffffffu, ss, m);
                    float nrm = sqrtf(ss);
                    float nc  = fminf(fmaxf(nrm, EPS), 1.0f - 1e-5f);
                    float f   = atanhf(nc) / nc;
                    v.x *= f; v.y *= f; v.z *= f; v.w *= f;
                } else {
                    const int* nb = g_csr + rg * DEGMAX;
                    int deg = g_hist[rg];
                    if (deg > DEGMAX) deg = DEGMAX;
                    float4 v1 = make_float4(0.f, 0.f, 0.f, 0.f);
                    float4 v2 = make_float4(0.f, 0.f, 0.f, 0.f);
                    float4 v3 = make_float4(0.f, 0.f, 0.f, 0.f);
                    int j = 0;
                    for (; j + 4 <= deg; j += 4) {
                        int s0 = nb[j], s1 = nb[j + 1], s2 = nb[j + 2], s3 = nb[j + 3];
                        f4add(v,  y4[s0 * 32 + lane]);
                        f4add(v1, y4[s1 * 32 + lane]);
                        f4add(v2, y4[s2 * 32 + lane]);
                        f4add(v3, y4[s3 * 32 + lane]);
                    }
                    for (; j < deg; j++)
                        f4add(v, y4[nb[j] * 32 + lane]);
                    f4add(v1, v2); f4add(v, v3); f4add(v, v1);
                    float inv = 1.0f / ((float)g_hist[rg] + EPS);
                    v.x *= inv; v.y *= inv; v.z *= inv; v.w *= inv;
                }
            }
            __nv_bfloat16 h0 = __float2bfloat16_rn(v.x), h1 = __float2bfloat16_rn(v.y);
            __nv_bfloat16 h2 = __float2bfloat16_rn(v.z), h3 = __float2bfloat16_rn(v.w);
            __nv_bfloat162 hp0(h0, h1), hp1(h2, h3);
            __nv_bfloat162 lp0(__float2bfloat16_rn(v.x - __bfloat162float(h0)),
                               __float2bfloat16_rn(v.y - __bfloat162float(h1)));
            __nv_bfloat162 lp1(__float2bfloat16_rn(v.z - __bfloat162float(h2)),
                               __float2bfloat16_rn(v.w - __bfloat162float(h3)));
            *(uint2*)(sb + OFF_AH + r * ROWB + lane * 8) =
                make_uint2(*(uint32_t*)&hp0, *(uint32_t*)&hp1);
            *(uint2*)(sb + OFF_AL + r * ROWB + lane * 8) =
                make_uint2(*(uint32_t*)&lp0, *(uint32_t*)&lp1);
        }
    }
    __syncthreads();

    float acc[2][8][4];

    // ---- GEMM1 ----
    #pragma unroll
    for (int ms = 0; ms < 2; ms++)
        #pragma unroll
        for (int ns = 0; ns < 8; ns++)
            #pragma unroll
            for (int j = 0; j < 4; j++) acc[ms][ns][j] = 0.f;
    do_gemm(Ah32, Al32, Wh32, Wl32, wm, wn, gid, tig, acc);
    __syncthreads();

    // ---- epilogue1: T = relu(acc + B1) -> Ah/Al ----
    #pragma unroll
    for (int ms = 0; ms < 2; ms++) {
        int r = wm * 32 + ms * 16 + gid;
        #pragma unroll
        for (int ns = 0; ns < 8; ns++) {
            int col = wn * 64 + ns * 8 + tig * 2;
            float b0 = B1s[col], b1 = B1s[col + 1];
            float v0 = fmaxf(acc[ms][ns][0] + b0, 0.f);
            float v1 = fmaxf(acc[ms][ns][1] + b1, 0.f);
            float v2 = fmaxf(acc[ms][ns][2] + b0, 0.f);
            float v3 = fmaxf(acc[ms][ns][3] + b1, 0.f);
            __nv_bfloat16 a0 = __float2bfloat16_rn(v0), a1 = __float2bfloat16_rn(v1);
            __nv_bfloat16 a2 = __float2bfloat16_rn(v2), a3 = __float2bfloat16_rn(v3);
            __nv_bfloat162 hA(a0, a1), hB(a2, a3);
            __nv_bfloat162 lA(__float2bfloat16_rn(v0 - __bfloat162float(a0)),
                              __float2bfloat16_rn(v1 - __bfloat162float(a1)));
            __nv_bfloat162 lB(__float2bfloat16_rn(v2 - __bfloat162float(a2)),
                              __float2bfloat16_rn(v3 - __bfloat162float(a3)));
            *(uint32_t*)(sb + OFF_AH + r * ROWB + col * 2)       = *(uint32_t*)&hA;
            *(uint32_t*)(sb + OFF_AL + r * ROWB + col * 2)       = *(uint32_t*)&lA;
            *(uint32_t*)(sb + OFF_AH + (r + 8) * ROWB + col * 2) = *(uint32_t*)&hB;
            *(uint32_t*)(sb + OFF_AL + (r + 8) * ROWB + col * 2) = *(uint32_t*)&lB;
        }
    }

    // ---- load W2 hi/lo ----
    {
        int m2 = mode * 2 + 1;
        const float4* sh = (const float4*)(g_wth + m2 * D * D);
        const float4* sl = (const float4*)(g_wtl + m2 * D * D);
        #pragma unroll
        for (int it = 0; it < 8; it++) {
            int idx = tid + it * 256;
            int n = idx >> 4, c = idx & 15;
            *(float4*)(sb + OFF_WH + n * ROWB + c * 16) = sh[idx];
            *(float4*)(sb + OFF_WL + n * ROWB + c * 16) = sl[idx];
        }
    }
    __syncthreads();

    // ---- GEMM2 ----
    #pragma unroll
    for (int ms = 0; ms < 2; ms++)
        #pragma unroll
        for (int ns = 0; ns < 8; ns++)
            #pragma unroll
            for (int j = 0; j < 4; j++) acc[ms][ns][j] = 0.f;
    do_gemm(Ah32, Al32, Wh32, Wl32, wm, wn, gid, tig, acc);

    if (mode == 0) {
        #pragma unroll
        for (int ms = 0; ms < 2; ms++) {
            int r = wm * 32 + ms * 16 + gid;
            #pragma unroll
            for (int ns = 0; ns < 8; ns++) {
                int col = wn * 64 + ns * 8 + tig * 2;
                float b0 = B2s[col], b1 = B2s[col + 1];
                int rg = row0 + r;
                if (rg < N)
                    *(float2*)(g_y + rg * D + col) =
                        make_float2(acc[ms][ns][0] + b0, acc[ms][ns][1] + b1);
                if (rg + 8 < N)
                    *(float2*)(g_y + (rg + 8) * D + col) =
                        make_float2(acc[ms][ns][2] + b0, acc[ms][ns][3] + b1);
            }
        }
    } else {
        __syncthreads();
        float* Sf = (float*)(sb + OFF_WH);
        #pragma unroll
        for (int ms = 0; ms < 2; ms++) {
            int r = wm * 32 + ms * 16 + gid;
            #pragma unroll
            for (int ns = 0; ns < 8; ns++) {
                int col = wn * 64 + ns * 8 + tig * 2;
                float b0 = B2s[col], b1 = B2s[col + 1];
                *(float2*)(Sf + r * SWF + col) =
                    make_float2(acc[ms][ns][0] + b0, acc[ms][ns][1] + b1);
                *(float2*)(Sf + (r + 8) * SWF + col) =
                    make_float2(acc[ms][ns][2] + b0, acc[ms][ns][3] + b1);
            }
        }
        __syncthreads();
        int r = tid >> 1, h = tid & 1;
        float ss = 0.f;
        float4 vv[16];
        #pragma unroll
        for (int j = 0; j < 16; j++) {
            float4 v = *(float4*)(Sf + r * SWF + h * 64 + j * 4);
            vv[j] = v;
            ss += v.x * v.x + v.y * v.y + v.z * v.z + v.w * v.w;
        }
        ss += __shfl_xor_sync(0xffffffffu, ss, 1);
        float nrm = sqrtf(ss);
        float nc  = fmaxf(nrm, EPS);
        float fm  = tanhf(nc) / nc;
        int rg = row0 + r;
        if (rg < N) {
            #pragma unroll
            for (int j = 0; j < 16; j++) {
                float4 v = vv[j];
                v.x *= fm; v.y *= fm; v.z *= fm; v.w *= fm;
                ((float4*)outp)[rg * 32 + h * 16 + j] = v;
            }
        }
    }
}

// ---------------- launch ----------------
extern "C" void kernel_launch(void* const* d_in, const int* in_sizes, int n_in,
                              void* d_out, int out_size) {
    const float* x      = (const float*)d_in[0];
    const int*   ei     = (const int*)d_in[1];
    const float* w_msg1 = (const float*)d_in[2];
    const float* b_msg1 = (const float*)d_in[3];
    const float* w_msg2 = (const float*)d_in[4];
    const float* b_msg2 = (const float*)d_in[5];
    const float* w_upd1 = (const float*)d_in[6];
    const float* b_upd1 = (const float*)d_in[7];
    const float* w_upd2 = (const float*)d_in[8];
    const float* b_upd2 = (const float*)d_in[9];
    float* out = (float*)d_out;

    int N = in_sizes[0] / D;
    int E = in_sizes[1] / 2;

    cudaFuncSetAttribute(mlp_tc_kernel,
                         cudaFuncAttributeMaxDynamicSharedMemorySize, SMEM_DYN);

    prep_w_kernel<<<64, 256>>>(w_msg1, w_msg2, w_upd1, w_upd2);
    zero_hist_kernel<<<(N + 255) / 256, 256>>>(N);
    fill_kernel<<<(E + 255) / 256, 256>>>(ei, E);

    int mblocks = (N + 127) / 128;
    mlp_tc_kernel<<<mblocks, 256, SMEM_DYN>>>(x, b_msg1, b_msg2, nullptr, N, 0);
    mlp_tc_kernel<<<mblocks, 256, SMEM_DYN>>>(nullptr, b_upd1, b_upd2, out, N, 1);
}

// round 6
// speedup vs baseline: 1.7523x; 1.2599x over previous
#include <cuda_runtime.h>
#include <cuda_bf16.h>
#include <cstdint>

#define D      128
#define TM     64
#define NMAX   50000
#define DEGMAX 128
#define EPS    1e-8f

#define ROWB  272           // bytes per bf16 tile row (136 bf16)
#define SWF   132           // f32 staging stride

// ---------------- scratch (static device globals) ----------------
__device__ float g_y[NMAX * D];
__device__ int   g_hist[NMAX];              // in-degree (atomic counters)
__device__ int   g_csr[NMAX * DEGMAX];      // padded neighbor buckets
// transposed + split weights: [mat][n][k] bf16; mat: 0=msg1,1=msg2,2=upd1,3=upd2
__device__ __nv_bfloat16 g_wth[4 * D * D];
__device__ __nv_bfloat16 g_wtl[4 * D * D];

// ---------------- smem layout (bytes) ----------------
#define OFF_AH 0u            /* 64 x 272  = 17408 */
#define OFF_AL 17408u
#define OFF_WH 34816u        /* 128 x 272 = 34816 */
#define OFF_WL 69632u
#define OFF_B1 104448u
#define OFF_B2 104960u
#define SMEM_DYN 105472u

// ---------------- PTX helpers ----------------
__device__ __forceinline__ uint32_t smem_u32(const void* p) {
    uint32_t a;
    asm("{ .reg .u64 t; cvta.to.shared.u64 t, %1; cvt.u32.u64 %0, t; }" : "=r"(a) : "l"(p));
    return a;
}
__device__ __forceinline__ void ldsm4(uint32_t* r, uint32_t addr) {
    asm volatile("ldmatrix.sync.aligned.m8n8.x4.shared.b16 {%0,%1,%2,%3}, [%4];"
        : "=r"(r[0]), "=r"(r[1]), "=r"(r[2]), "=r"(r[3]) : "r"(addr));
}
__device__ __forceinline__ void mma16816(float* c, const uint32_t* a,
                                         uint32_t b0, uint32_t b1) {
    asm volatile(
        "mma.sync.aligned.m16n8k16.row.col.f32.bf16.bf16.f32 "
        "{%0,%1,%2,%3}, {%4,%5,%6,%7}, {%8,%9}, {%0,%1,%2,%3};"
        : "+f"(c[0]), "+f"(c[1]), "+f"(c[2]), "+f"(c[3])
        : "r"(a[0]), "r"(a[1]), "r"(a[2]), "r"(a[3]), "r"(b0), "r"(b1));
}

// 3-term split GEMM (M64 tile): acc += (Ah+Al) @ (Wh+Wl)^T  (dropping Al*Wl)
// warp computes 32 rows (wm) x 32 cols (wn); frag loads via ldmatrix.x4
__device__ __forceinline__ void do_gemm(
    uint32_t sAH, uint32_t sAL, uint32_t sWH, uint32_t sWL,
    int wm, int wn, int lane, float acc[2][4][4])
{
    const uint32_t lrow = (uint32_t)(lane & 15) * ROWB + (uint32_t)(lane >> 4) * 16;
    const uint32_t aoff = (uint32_t)(wm * 32) * ROWB + lrow;
    const uint32_t woff = (uint32_t)(wn * 32) * ROWB + lrow;

    #pragma unroll
    for (int ks = 0; ks < 8; ks++) {
        const uint32_t kb = (uint32_t)ks * 32;
        uint32_t ah[2][4], al[2][4], wh[2][4], wl[2][4];
        #pragma unroll
        for (int ms = 0; ms < 2; ms++) {
            ldsm4(ah[ms], sAH + aoff + ms * 16 * ROWB + kb);
            ldsm4(al[ms], sAL + aoff + ms * 16 * ROWB + kb);
        }
        #pragma unroll
        for (int np = 0; np < 2; np++) {
            ldsm4(wh[np], sWH + woff + np * 16 * ROWB + kb);
            ldsm4(wl[np], sWL + woff + np * 16 * ROWB + kb);
        }
        #pragma unroll
        for (int np = 0; np < 2; np++)
            #pragma unroll
            for (int h = 0; h < 2; h++) {
                uint32_t bh0 = wh[np][h], bh1 = wh[np][h + 2];
                uint32_t bl0 = wl[np][h], bl1 = wl[np][h + 2];
                #pragma unroll
                for (int ms = 0; ms < 2; ms++) {
                    float* c = acc[ms][np * 2 + h];
                    mma16816(c, ah[ms], bh0, bh1);
                    mma16816(c, ah[ms], bl0, bl1);
                    mma16816(c, al[ms], bh0, bh1);
                }
            }
    }
}

// ---------------- bucket-CSR build ----------------
__global__ void zero_hist_kernel(int n) {
    int i = blockIdx.x * blockDim.x + threadIdx.x;
    if (i < n) g_hist[i] = 0;
}
__global__ void fill_kernel(const int* __restrict__ ei, int E) {
    int e = blockIdx.x * blockDim.x + threadIdx.x;
    if (e < E) {
        int dst = ei[e];
        int src = ei[E + e];
        int pos = atomicAdd(&g_hist[dst], 1);
        if (pos < DEGMAX) g_csr[dst * DEGMAX + pos] = src;
    }
}

// transpose + bf16 hi/lo split of the 4 weight matrices
__global__ void prep_w_kernel(const float* __restrict__ w0, const float* __restrict__ w1,
                              const float* __restrict__ w2, const float* __restrict__ w3) {
    int g = blockIdx.x * blockDim.x + threadIdx.x;    // 0..16383
    int mat = g >> 12;
    int rem = g & 4095;
    int k = rem >> 5;
    int n4 = rem & 31;
    const float* W = (mat == 0) ? w0 : (mat == 1) ? w1 : (mat == 2) ? w2 : w3;
    float4 v = ((const float4*)W)[k * 32 + n4];
    float a[4] = {v.x, v.y, v.z, v.w};
    #pragma unroll
    for (int j = 0; j < 4; j++) {
        int n = n4 * 4 + j;
        float f = a[j];
        __nv_bfloat16 hi = __float2bfloat16_rn(f);
        __nv_bfloat16 lo = __float2bfloat16_rn(f - __bfloat162float(hi));
        g_wth[mat * D * D + n * D + k] = hi;
        g_wtl[mat * D * D + n * D + k] = lo;
    }
}

__device__ __forceinline__ void f4add(float4& a, const float4 b) {
    a.x += b.x; a.y += b.y; a.z += b.z; a.w += b.w;
}

// ---------------- fused MLP via mma.sync (HMMA), TM=64, 2 CTAs/SM ----------------
// mode 0: g_y = MLP1(logmap0(x))
// mode 1: out = expmap0(MLP2(mean_{bucket} g_y[src]))
__global__ __launch_bounds__(256, 2) void mlp_tc_kernel(
    const float* __restrict__ xin,
    const float* __restrict__ B1v, const float* __restrict__ B2v,
    float* __restrict__ outp, int N, int mode)
{
    extern __shared__ char sb[];
    const uint32_t sbase = smem_u32(sb);
    float* B1s = (float*)(sb + OFF_B1);
    float* B2s = (float*)(sb + OFF_B2);

    const int tid  = threadIdx.x;
    const int wid  = tid >> 5;
    const int lane = tid & 31;
    const int gid  = lane >> 2;
    const int tig  = lane & 3;
    const int wm   = wid & 1;          // 2 x M32
    const int wn   = wid >> 1;         // 4 x N32
    const int row0 = blockIdx.x * TM;

    if (tid < 128) B1s[tid] = B1v[tid];
    else           B2s[tid - 128] = B2v[tid - 128];

    // ---- load W1 hi/lo into smem ----
    {
        int m1 = mode * 2;
        const float4* sh = (const float4*)(g_wth + m1 * D * D);
        const float4* sl = (const float4*)(g_wtl + m1 * D * D);
        #pragma unroll
        for (int it = 0; it < 8; it++) {
            int idx = tid + it * 256;          // 2048 float4 per matrix
            int n = idx >> 4, c = idx & 15;
            *(float4*)(sb + OFF_WH + n * ROWB + c * 16) = sh[idx];
            *(float4*)(sb + OFF_WL + n * ROWB + c * 16) = sl[idx];
        }
    }

    // ---- input rows: logmap0(x) (mode 0) or bucket-gather mean (mode 1) ----
    {
        const float4* x4 = (const float4*)xin;
        const float4* y4 = (const float4*)g_y;
        #pragma unroll 2
        for (int i = 0; i < 8; i++) {
            int r = wid * 8 + i;
            int rg = row0 + r;
            float4 v = make_float4(0.f, 0.f, 0.f, 0.f);
            if (rg < N) {
                if (mode == 0) {
                    v = x4[rg * 32 + lane];
                    float ss = v.x * v.x + v.y * v.y + v.z * v.z + v.w * v.w;
                    #pragma unroll
                    for (int m = 16; m >= 1; m >>= 1) ss += __shfl_xor_sync(0xffffffffu, ss, m);
                    float nrm = sqrtf(ss);
                    float nc  = fminf(fmaxf(nrm, EPS), 1.0f - 1e-5f);
                    float f   = atanhf(nc) / nc;
                    v.x *= f; v.y *= f; v.z *= f; v.w *= f;
                } else {
                    const int* nb = g_csr + rg * DEGMAX;
                    int deg = g_hist[rg];
                    if (deg > DEGMAX) deg = DEGMAX;
                    float4 v1 = make_float4(0.f, 0.f, 0.f, 0.f);
                    float4 v2 = make_float4(0.f, 0.f, 0.f, 0.f);
                    float4 v3 = make_float4(0.f, 0.f, 0.f, 0.f);
                    int j = 0;
                    for (; j + 4 <= deg; j += 4) {
                        int s0 = nb[j], s1 = nb[j + 1], s2 = nb[j + 2], s3 = nb[j + 3];
                        f4add(v,  y4[s0 * 32 + lane]);
                        f4add(v1, y4[s1 * 32 + lane]);
                        f4add(v2, y4[s2 * 32 + lane]);
                        f4add(v3, y4[s3 * 32 + lane]);
                    }
                    for (; j < deg; j++)
                        f4add(v, y4[nb[j] * 32 + lane]);
                    f4add(v1, v2); f4add(v, v3); f4add(v, v1);
                    float inv = 1.0f / ((float)g_hist[rg] + EPS);
                    v.x *= inv; v.y *= inv; v.z *= inv; v.w *= inv;
                }
            }
            __nv_bfloat16 h0 = __float2bfloat16_rn(v.x), h1 = __float2bfloat16_rn(v.y);
            __nv_bfloat16 h2 = __float2bfloat16_rn(v.z), h3 = __float2bfloat16_rn(v.w);
            __nv_bfloat162 hp0(h0, h1), hp1(h2, h3);
            __nv_bfloat162 lp0(__float2bfloat16_rn(v.x - __bfloat162float(h0)),
                               __float2bfloat16_rn(v.y - __bfloat162float(h1)));
            __nv_bfloat162 lp1(__float2bfloat16_rn(v.z - __bfloat162float(h2)),
                               __float2bfloat16_rn(v.w - __bfloat162float(h3)));
            *(uint2*)(sb + OFF_AH + r * ROWB + lane * 8) =
                make_uint2(*(uint32_t*)&hp0, *(uint32_t*)&hp1);
            *(uint2*)(sb + OFF_AL + r * ROWB + lane * 8) =
                make_uint2(*(uint32_t*)&lp0, *(uint32_t*)&lp1);
        }
    }
    __syncthreads();

    float acc[2][4][4];

    // ---- GEMM1 ----
    #pragma unroll
    for (int ms = 0; ms < 2; ms++)
        #pragma unroll
        for (int ns = 0; ns < 4; ns++)
            #pragma unroll
            for (int j = 0; j < 4; j++) acc[ms][ns][j] = 0.f;
    do_gemm(sbase + OFF_AH, sbase + OFF_AL, sbase + OFF_WH, sbase + OFF_WL,
            wm, wn, lane, acc);
    __syncthreads();

    // ---- epilogue1: T = relu(acc + B1) -> Ah/Al ----
    #pragma unroll
    for (int ms = 0; ms < 2; ms++) {
        int r = wm * 32 + ms * 16 + gid;
        #pragma unroll
        for (int ns = 0; ns < 4; ns++) {
            int col = wn * 32 + ns * 8 + tig * 2;
            float b0 = B1s[col], b1 = B1s[col + 1];
            float v0 = fmaxf(acc[ms][ns][0] + b0, 0.f);
            float v1 = fmaxf(acc[ms][ns][1] + b1, 0.f);
            float v2 = fmaxf(acc[ms][ns][2] + b0, 0.f);
            float v3 = fmaxf(acc[ms][ns][3] + b1, 0.f);
            __nv_bfloat16 a0 = __float2bfloat16_rn(v0), a1 = __float2bfloat16_rn(v1);
            __nv_bfloat16 a2 = __float2bfloat16_rn(v2), a3 = __float2bfloat16_rn(v3);
            __nv_bfloat162 hA(a0, a1), hB(a2, a3);
            __nv_bfloat162 lA(__float2bfloat16_rn(v0 - __bfloat162float(a0)),
                              __float2bfloat16_rn(v1 - __bfloat162float(a1)));
            __nv_bfloat162 lB(__float2bfloat16_rn(v2 - __bfloat162float(a2)),
                              __float2bfloat16_rn(v3 - __bfloat162float(a3)));
            *(uint32_t*)(sb + OFF_AH + r * ROWB + col * 2)       = *(uint32_t*)&hA;
            *(uint32_t*)(sb + OFF_AL + r * ROWB + col * 2)       = *(uint32_t*)&lA;
            *(uint32_t*)(sb + OFF_AH + (r + 8) * ROWB + col * 2) = *(uint32_t*)&hB;
            *(uint32_t*)(sb + OFF_AL + (r + 8) * ROWB + col * 2) = *(uint32_t*)&lB;
        }
    }

    // ---- load W2 hi/lo ----
    {
        int m2 = mode * 2 + 1;
        const float4* sh = (const float4*)(g_wth + m2 * D * D);
        const float4* sl = (const float4*)(g_wtl + m2 * D * D);
        #pragma unroll
        for (int it = 0; it < 8; it++) {
            int idx = tid + it * 256;
            int n = idx >> 4, c = idx & 15;
            *(float4*)(sb + OFF_WH + n * ROWB + c * 16) = sh[idx];
            *(float4*)(sb + OFF_WL + n * ROWB + c * 16) = sl[idx];
        }
    }
    __syncthreads();

    // ---- GEMM2 ----
    #pragma unroll
    for (int ms = 0; ms < 2; ms++)
        #pragma unroll
        for (int ns = 0; ns < 4; ns++)
            #pragma unroll
            for (int j = 0; j < 4; j++) acc[ms][ns][j] = 0.f;
    do_gemm(sbase + OFF_AH, sbase + OFF_AL, sbase + OFF_WH, sbase + OFF_WL,
            wm, wn, lane, acc);

    if (mode == 0) {
        #pragma unroll
        for (int ms = 0; ms < 2; ms++) {
            int r = wm * 32 + ms * 16 + gid;
            #pragma unroll
            for (int ns = 0; ns < 4; ns++) {
                int col = wn * 32 + ns * 8 + tig * 2;
                float b0 = B2s[col], b1 = B2s[col + 1];
                int rg = row0 + r;
                if (rg < N)
                    *(float2*)(g_y + rg * D + col) =
                        make_float2(acc[ms][ns][0] + b0, acc[ms][ns][1] + b1);
                if (rg + 8 < N)
                    *(float2*)(g_y + (rg + 8) * D + col) =
                        make_float2(acc[ms][ns][2] + b0, acc[ms][ns][3] + b1);
            }
        }
    } else {
        __syncthreads();
        float* Sf = (float*)(sb + OFF_WH);        // 64 x 132 f32 staging
        #pragma unroll
        for (int ms = 0; ms < 2; ms++) {
            int r = wm * 32 + ms * 16 + gid;
            #pragma unroll
            for (int ns = 0; ns < 4; ns++) {
                int col = wn * 32 + ns * 8 + tig * 2;
                float b0 = B2s[col], b1 = B2s[col + 1];
                *(float2*)(Sf + r * SWF + col) =
                    make_float2(acc[ms][ns][0] + b0, acc[ms][ns][1] + b1);
                *(float2*)(Sf + (r + 8) * SWF + col) =
                    make_float2(acc[ms][ns][2] + b0, acc[ms][ns][3] + b1);
            }
        }
        __syncthreads();
        // expmap0: 4 threads per row
        int r = tid >> 2, q = tid & 3;
        float ss = 0.f;
        float4 vv[8];
        #pragma unroll
        for (int j = 0; j < 8; j++) {
            float4 v = *(float4*)(Sf + r * SWF + q * 32 + j * 4);
            vv[j] = v;
            ss += v.x * v.x + v.y * v.y + v.z * v.z + v.w * v.w;
        }
        ss += __shfl_xor_sync(0xffffffffu, ss, 1);
        ss += __shfl_xor_sync(0xffffffffu, ss, 2);
        float nrm = sqrtf(ss);
        float nc  = fmaxf(nrm, EPS);
        float fm  = tanhf(nc) / nc;
        int rg = row0 + r;
        if (rg < N) {
            #pragma unroll
            for (int j = 0; j < 8; j++) {
                float4 v = vv[j];
                v.x *= fm; v.y *= fm; v.z *= fm; v.w *= fm;
                ((float4*)outp)[rg * 32 + q * 8 + j] = v;
            }
        }
    }
}

// ---------------- launch ----------------
extern "C" void kernel_launch(void* const* d_in, const int* in_sizes, int n_in,
                              void* d_out, int out_size) {
    const float* x      = (const float*)d_in[0];
    const int*   ei     = (const int*)d_in[1];
    const float* w_msg1 = (const float*)d_in[2];
    const float* b_msg1 = (const float*)d_in[3];
    const float* w_msg2 = (const float*)d_in[4];
    const float* b_msg2 = (const float*)d_in[5];
    const float* w_upd1 = (const float*)d_in[6];
    const float* b_upd1 = (const float*)d_in[7];
    const float* w_upd2 = (const float*)d_in[8];
    const float* b_upd2 = (const float*)d_in[9];
    float* out = (float*)d_out;

    int N = in_sizes[0] / D;
    int E = in_sizes[1] / 2;

    cudaFuncSetAttribute(mlp_tc_kernel,
                         cudaFuncAttributeMaxDynamicSharedMemorySize, SMEM_DYN);

    prep_w_kernel<<<64, 256>>>(w_msg1, w_msg2, w_upd1, w_upd2);
    zero_hist_kernel<<<(N + 255) / 256, 256>>>(N);
    fill_kernel<<<(E + 255) / 256, 256>>>(ei, E);

    int mblocks = (N + TM - 1) / TM;
    mlp_tc_kernel<<<mblocks, 256, SMEM_DYN>>>(x, b_msg1, b_msg2, nullptr, N, 0);
    mlp_tc_kernel<<<mblocks, 256, SMEM_DYN>>>(nullptr, b_upd1, b_upd2, out, N, 1);
}

// round 7
// speedup vs baseline: 1.7572x; 1.0028x over previous
#include <cuda_runtime.h>
#include <cuda_bf16.h>
#include <cstdint>

#define D      128
#define TM     64
#define NMAX   50000
#define DEGMAX 128
#define EPS    1e-8f

#define ROWB  272           // bytes per bf16 tile row (136 bf16)
#define SWF   132           // f32 staging stride

// ---------------- scratch (static device globals) ----------------
__device__ float g_y[NMAX * D];
__device__ int   g_hist[NMAX];              // in-degree (atomic counters)
__device__ int   g_csr[NMAX * DEGMAX];      // padded neighbor buckets
// transposed + split weights: [mat][n][k] bf16; mat: 0=msg1,1=msg2,2=upd1,3=upd2
__device__ __nv_bfloat16 g_wth[4 * D * D];
__device__ __nv_bfloat16 g_wtl[4 * D * D];

// ---------------- smem layout (bytes) ----------------
#define OFF_AH 0u            /* 64 x 272  = 17408 */
#define OFF_AL 17408u
#define OFF_WH 34816u        /* 128 x 272 = 34816 */
#define OFF_WL 69632u
#define OFF_B1 104448u
#define OFF_B2 104960u
#define SMEM_DYN 105472u

// ---------------- PTX helpers ----------------
__device__ __forceinline__ uint32_t smem_u32(const void* p) {
    uint32_t a;
    asm("{ .reg .u64 t; cvta.to.shared.u64 t, %1; cvt.u32.u64 %0, t; }" : "=r"(a) : "l"(p));
    return a;
}
__device__ __forceinline__ void ldsm4(uint32_t* r, uint32_t addr) {
    asm volatile("ldmatrix.sync.aligned.m8n8.x4.shared.b16 {%0,%1,%2,%3}, [%4];"
        : "=r"(r[0]), "=r"(r[1]), "=r"(r[2]), "=r"(r[3]) : "r"(addr));
}
// no volatile: pure register dataflow, let the scheduler move these
__device__ __forceinline__ void mma16816(float* c, const uint32_t* a,
                                         uint32_t b0, uint32_t b1) {
    asm("mma.sync.aligned.m16n8k16.row.col.f32.bf16.bf16.f32 "
        "{%0,%1,%2,%3}, {%4,%5,%6,%7}, {%8,%9}, {%0,%1,%2,%3};"
        : "+f"(c[0]), "+f"(c[1]), "+f"(c[2]), "+f"(c[3])
        : "r"(a[0]), "r"(a[1]), "r"(a[2]), "r"(a[3]), "r"(b0), "r"(b1));
}

// 3-term split GEMM (M64 tile): acc += (Ah+Al) @ (Wh+Wl)^T  (dropping Al*Wl)
// warp computes 32 rows (wm) x 32 cols (wn); frag loads via ldmatrix.x4
// MMA issue order is TERM-MAJOR: all 8 independent acc chains per term, so
// dependent MMAs on one accumulator are separated by 7 independent ones.
__device__ __forceinline__ void do_gemm(
    uint32_t sAH, uint32_t sAL, uint32_t sWH, uint32_t sWL,
    int wm, int wn, int lane, float acc[2][4][4])
{
    const uint32_t lrow = (uint32_t)(lane & 15) * ROWB + (uint32_t)(lane >> 4) * 16;
    const uint32_t aoff = (uint32_t)(wm * 32) * ROWB + lrow;
    const uint32_t woff = (uint32_t)(wn * 32) * ROWB + lrow;

    #pragma unroll
    for (int ks = 0; ks < 8; ks++) {
        const uint32_t kb = (uint32_t)ks * 32;
        uint32_t ah[2][4], al[2][4], wh[2][4], wl[2][4];
        #pragma unroll
        for (int ms = 0; ms < 2; ms++) {
            ldsm4(ah[ms], sAH + aoff + ms * 16 * ROWB + kb);
            ldsm4(al[ms], sAL + aoff + ms * 16 * ROWB + kb);
        }
        #pragma unroll
        for (int np = 0; np < 2; np++) {
            ldsm4(wh[np], sWH + woff + np * 16 * ROWB + kb);
            ldsm4(wl[np], sWL + woff + np * 16 * ROWB + kb);
        }
        // term 1: Ah * Wh  (8 independent chains)
        #pragma unroll
        for (int np = 0; np < 2; np++)
            #pragma unroll
            for (int h = 0; h < 2; h++)
                #pragma unroll
                for (int ms = 0; ms < 2; ms++)
                    mma16816(acc[ms][np * 2 + h], ah[ms], wh[np][h], wh[np][h + 2]);
        // term 2: Ah * Wl
        #pragma unroll
        for (int np = 0; np < 2; np++)
            #pragma unroll
            for (int h = 0; h < 2; h++)
                #pragma unroll
                for (int ms = 0; ms < 2; ms++)
                    mma16816(acc[ms][np * 2 + h], ah[ms], wl[np][h], wl[np][h + 2]);
        // term 3: Al * Wh
        #pragma unroll
        for (int np = 0; np < 2; np++)
            #pragma unroll
            for (int h = 0; h < 2; h++)
                #pragma unroll
                for (int ms = 0; ms < 2; ms++)
                    mma16816(acc[ms][np * 2 + h], al[ms], wh[np][h], wh[np][h + 2]);
    }
}

// ---------------- bucket-CSR build ----------------
__global__ void zero_hist_kernel(int n) {
    int i = blockIdx.x * blockDim.x + threadIdx.x;
    if (i < n) g_hist[i] = 0;
}
__global__ void fill_kernel(const int* __restrict__ ei, int E) {
    int e = blockIdx.x * blockDim.x + threadIdx.x;
    if (e < E) {
        int dst = ei[e];
        int src = ei[E + e];
        int pos = atomicAdd(&g_hist[dst], 1);
        if (pos < DEGMAX) g_csr[dst * DEGMAX + pos] = src;
    }
}

// transpose + bf16 hi/lo split of the 4 weight matrices
__global__ void prep_w_kernel(const float* __restrict__ w0, const float* __restrict__ w1,
                              const float* __restrict__ w2, const float* __restrict__ w3) {
    int g = blockIdx.x * blockDim.x + threadIdx.x;    // 0..16383
    int mat = g >> 12;
    int rem = g & 4095;
    int k = rem >> 5;
    int n4 = rem & 31;
    const float* W = (mat == 0) ? w0 : (mat == 1) ? w1 : (mat == 2) ? w2 : w3;
    float4 v = ((const float4*)W)[k * 32 + n4];
    float a[4] = {v.x, v.y, v.z, v.w};
    #pragma unroll
    for (int j = 0; j < 4; j++) {
        int n = n4 * 4 + j;
        float f = a[j];
        __nv_bfloat16 hi = __float2bfloat16_rn(f);
        __nv_bfloat16 lo = __float2bfloat16_rn(f - __bfloat162float(hi));
        g_wth[mat * D * D + n * D + k] = hi;
        g_wtl[mat * D * D + n * D + k] = lo;
    }
}

__device__ __forceinline__ void f4add(float4& a, const float4 b) {
    a.x += b.x; a.y += b.y; a.z += b.z; a.w += b.w;
}

// ---------------- fused MLP via mma.sync (HMMA), TM=64, 2 CTAs/SM ----------------
// mode 0: g_y = MLP1(logmap0(x))
// mode 1: out = expmap0(MLP2(mean_{bucket} g_y[src]))
__global__ __launch_bounds__(256, 2) void mlp_tc_kernel(
    const float* __restrict__ xin,
    const float* __restrict__ B1v, const float* __restrict__ B2v,
    float* __restrict__ outp, int N, int mode)
{
    extern __shared__ char sb[];
    const uint32_t sbase = smem_u32(sb);
    float* B1s = (float*)(sb + OFF_B1);
    float* B2s = (float*)(sb + OFF_B2);

    const int tid  = threadIdx.x;
    const int wid  = tid >> 5;
    const int lane = tid & 31;
    const int gid  = lane >> 2;
    const int tig  = lane & 3;
    const int wm   = wid & 1;          // 2 x M32
    const int wn   = wid >> 1;         // 4 x N32
    const int row0 = blockIdx.x * TM;

    if (tid < 128) B1s[tid] = B1v[tid];
    else           B2s[tid - 128] = B2v[tid - 128];

    // ---- load W1 hi/lo into smem ----
    {
        int m1 = mode * 2;
        const float4* sh = (const float4*)(g_wth + m1 * D * D);
        const float4* sl = (const float4*)(g_wtl + m1 * D * D);
        #pragma unroll
        for (int it = 0; it < 8; it++) {
            int idx = tid + it * 256;          // 2048 float4 per matrix
            int n = idx >> 4, c = idx & 15;
            *(float4*)(sb + OFF_WH + n * ROWB + c * 16) = sh[idx];
            *(float4*)(sb + OFF_WL + n * ROWB + c * 16) = sl[idx];
        }
    }

    // ---- input rows: logmap0(x) (mode 0) or bucket-gather mean (mode 1) ----
    {
        const float4* x4 = (const float4*)xin;
        const float4* y4 = (const float4*)g_y;
        #pragma unroll 2
        for (int i = 0; i < 8; i++) {
            int r = wid * 8 + i;
            int rg = row0 + r;
            float4 v = make_float4(0.f, 0.f, 0.f, 0.f);
            if (rg < N) {
                if (mode == 0) {
                    v = x4[rg * 32 + lane];
                    float ss = v.x * v.x + v.y * v.y + v.z * v.z + v.w * v.w;
                    #pragma unroll
                    for (int m = 16; m >= 1; m >>= 1) ss += __shfl_xor_sync(0xffffffffu, ss, m);
                    float nrm = sqrtf(ss);
                    float nc  = fminf(fmaxf(nrm, EPS), 1.0f - 1e-5f);
                    float f   = atanhf(nc) / nc;
                    v.x *= f; v.y *= f; v.z *= f; v.w *= f;
                } else {
                    const int* nb = g_csr + rg * DEGMAX;
                    int deg = g_hist[rg];
                    if (deg > DEGMAX) deg = DEGMAX;
                    float4 v1 = make_float4(0.f, 0.f, 0.f, 0.f);
                    float4 v2 = make_float4(0.f, 0.f, 0.f, 0.f);
                    float4 v3 = make_float4(0.f, 0.f, 0.f, 0.f);
                    int j = 0;
                    for (; j + 4 <= deg; j += 4) {
                        int s0 = nb[j], s1 = nb[j + 1], s2 = nb[j + 2], s3 = nb[j + 3];
                        f4add(v,  y4[s0 * 32 + lane]);
                        f4add(v1, y4[s1 * 32 + lane]);
                        f4add(v2, y4[s2 * 32 + lane]);
                        f4add(v3, y4[s3 * 32 + lane]);
                    }
                    for (; j < deg; j++)
                        f4add(v, y4[nb[j] * 32 + lane]);
                    f4add(v1, v2); f4add(v, v3); f4add(v, v1);
                    float inv = 1.0f / ((float)g_hist[rg] + EPS);
                    v.x *= inv; v.y *= inv; v.z *= inv; v.w *= inv;
                }
            }
            __nv_bfloat16 h0 = __float2bfloat16_rn(v.x), h1 = __float2bfloat16_rn(v.y);
            __nv_bfloat16 h2 = __float2bfloat16_rn(v.z), h3 = __float2bfloat16_rn(v.w);
            __nv_bfloat162 hp0(h0, h1), hp1(h2, h3);
            __nv_bfloat162 lp0(__float2bfloat16_rn(v.x - __bfloat162float(h0)),
                               __float2bfloat16_rn(v.y - __bfloat162float(h1)));
            __nv_bfloat162 lp1(__float2bfloat16_rn(v.z - __bfloat162float(h2)),
                               __float2bfloat16_rn(v.w - __bfloat162float(h3)));
            *(uint2*)(sb + OFF_AH + r * ROWB + lane * 8) =
                make_uint2(*(uint32_t*)&hp0, *(uint32_t*)&hp1);
            *(uint2*)(sb + OFF_AL + r * ROWB + lane * 8) =
                make_uint2(*(uint32_t*)&lp0, *(uint32_t*)&lp1);
        }
    }
    __syncthreads();

    float acc[2][4][4];

    // ---- GEMM1 ----
    #pragma unroll
    for (int ms = 0; ms < 2; ms++)
        #pragma unroll
        for (int ns = 0; ns < 4; ns++)
            #pragma unroll
            for (int j = 0; j < 4; j++) acc[ms][ns][j] = 0.f;
    do_gemm(sbase + OFF_AH, sbase + OFF_AL, sbase + OFF_WH, sbase + OFF_WL,
            wm, wn, lane, acc);
    __syncthreads();

    // ---- epilogue1: T = relu(acc + B1) -> Ah/Al ----
    #pragma unroll
    for (int ms = 0; ms < 2; ms++) {
        int r = wm * 32 + ms * 16 + gid;
        #pragma unroll
        for (int ns = 0; ns < 4; ns++) {
            int col = wn * 32 + ns * 8 + tig * 2;
            float b0 = B1s[col], b1 = B1s[col + 1];
            float v0 = fmaxf(acc[ms][ns][0] + b0, 0.f);
            float v1 = fmaxf(acc[ms][ns][1] + b1, 0.f);
            float v2 = fmaxf(acc[ms][ns][2] + b0, 0.f);
            float v3 = fmaxf(acc[ms][ns][3] + b1, 0.f);
            __nv_bfloat16 a0 = __float2bfloat16_rn(v0), a1 = __float2bfloat16_rn(v1);
            __nv_bfloat16 a2 = __float2bfloat16_rn(v2), a3 = __float2bfloat16_rn(v3);
            __nv_bfloat162 hA(a0, a1), hB(a2, a3);
            __nv_bfloat162 lA(__float2bfloat16_rn(v0 - __bfloat162float(a0)),
                              __float2bfloat16_rn(v1 - __bfloat162float(a1)));
            __nv_bfloat162 lB(__float2bfloat16_rn(v2 - __bfloat162float(a2)),
                              __float2bfloat16_rn(v3 - __bfloat162float(a3)));
            *(uint32_t*)(sb + OFF_AH + r * ROWB + col * 2)       = *(uint32_t*)&hA;
            *(uint32_t*)(sb + OFF_AL + r * ROWB + col * 2)       = *(uint32_t*)&lA;
            *(uint32_t*)(sb + OFF_AH + (r + 8) * ROWB + col * 2) = *(uint32_t*)&hB;
            *(uint32_t*)(sb + OFF_AL + (r + 8) * ROWB + col * 2) = *(uint32_t*)&lB;
        }
    }

    // ---- load W2 hi/lo ----
    {
        int m2 = mode * 2 + 1;
        const float4* sh = (const float4*)(g_wth + m2 * D * D);
        const float4* sl = (const float4*)(g_wtl + m2 * D * D);
        #pragma unroll
        for (int it = 0; it < 8; it++) {
            int idx = tid + it * 256;
            int n = idx >> 4, c = idx & 15;
            *(float4*)(sb + OFF_WH + n * ROWB + c * 16) = sh[idx];
            *(float4*)(sb + OFF_WL + n * ROWB + c * 16) = sl[idx];
        }
    }
    __syncthreads();

    // ---- GEMM2 ----
    #pragma unroll
    for (int ms = 0; ms < 2; ms++)
        #pragma unroll
        for (int ns = 0; ns < 4; ns++)
            #pragma unroll
            for (int j = 0; j < 4; j++) acc[ms][ns][j] = 0.f;
    do_gemm(sbase + OFF_AH, sbase + OFF_AL, sbase + OFF_WH, sbase + OFF_WL,
            wm, wn, lane, acc);

    if (mode == 0) {
        #pragma unroll
        for (int ms = 0; ms < 2; ms++) {
            int r = wm * 32 + ms * 16 + gid;
            #pragma unroll
            for (int ns = 0; ns < 4; ns++) {
                int col = wn * 32 + ns * 8 + tig * 2;
                float b0 = B2s[col], b1 = B2s[col + 1];
                int rg = row0 + r;
                if (rg < N)
                    *(float2*)(g_y + rg * D + col) =
                        make_float2(acc[ms][ns][0] + b0, acc[ms][ns][1] + b1);
                if (rg + 8 < N)
                    *(float2*)(g_y + (rg + 8) * D + col) =
                        make_float2(acc[ms][ns][2] + b0, acc[ms][ns][3] + b1);
            }
        }
    } else {
        __syncthreads();
        float* Sf = (float*)(sb + OFF_WH);        // 64 x 132 f32 staging
        #pragma unroll
        for (int ms = 0; ms < 2; ms++) {
            int r = wm * 32 + ms * 16 + gid;
            #pragma unroll
            for (int ns = 0; ns < 4; ns++) {
                int col = wn * 32 + ns * 8 + tig * 2;
                float b0 = B2s[col], b1 = B2s[col + 1];
                *(float2*)(Sf + r * SWF + col) =
                    make_float2(acc[ms][ns][0] + b0, acc[ms][ns][1] + b1);
                *(float2*)(Sf + (r + 8) * SWF + col) =
                    make_float2(acc[ms][ns][2] + b0, acc[ms][ns][3] + b1);
            }
        }
        __syncthreads();
        // expmap0: 4 threads per row
        int r = tid >> 2, q = tid & 3;
        float ss = 0.f;
        float4 vv[8];
        #pragma unroll
        for (int j = 0; j < 8; j++) {
            float4 v = *(float4*)(Sf + r * SWF + q * 32 + j * 4);
            vv[j] = v;
            ss += v.x * v.x + v.y * v.y + v.z * v.z + v.w * v.w;
        }
        ss += __shfl_xor_sync(0xffffffffu, ss, 1);
        ss += __shfl_xor_sync(0xffffffffu, ss, 2);
        float nrm = sqrtf(ss);
        float nc  = fmaxf(nrm, EPS);
        float fm  = tanhf(nc) / nc;
        int rg = row0 + r;
        if (rg < N) {
            #pragma unroll
            for (int j = 0; j < 8; j++) {
                float4 v = vv[j];
                v.x *= fm; v.y *= fm; v.z *= fm; v.w *= fm;
                ((float4*)outp)[rg * 32 + q * 8 + j] = v;
            }
        }
    }
}

// ---------------- launch ----------------
extern "C" void kernel_launch(void* const* d_in, const int* in_sizes, int n_in,
                              void* d_out, int out_size) {
    const float* x      = (const float*)d_in[0];
    const int*   ei     = (const int*)d_in[1];
    const float* w_msg1 = (const float*)d_in[2];
    const float* b_msg1 = (const float*)d_in[3];
    const float* w_msg2 = (const float*)d_in[4];
    const float* b_msg2 = (const float*)d_in[5];
    const float* w_upd1 = (const float*)d_in[6];
    const float* b_upd1 = (const float*)d_in[7];
    const float* w_upd2 = (const float*)d_in[8];
    const float* b_upd2 = (const float*)d_in[9];
    float* out = (float*)d_out;

    int N = in_sizes[0] / D;
    int E = in_sizes[1] / 2;

    cudaFuncSetAttribute(mlp_tc_kernel,
                         cudaFuncAttributeMaxDynamicSharedMemorySize, SMEM_DYN);

    prep_w_kernel<<<64, 256>>>(w_msg1, w_msg2, w_upd1, w_upd2);
    zero_hist_kernel<<<(N + 255) / 256, 256>>>(N);
    fill_kernel<<<(E + 255) / 256, 256>>>(ei, E);

    int mblocks = (N + TM - 1) / TM;
    mlp_tc_kernel<<<mblocks, 256, SMEM_DYN>>>(x, b_msg1, b_msg2, nullptr, N, 0);
    mlp_tc_kernel<<<mblocks, 256, SMEM_DYN>>>(nullptr, b_upd1, b_upd2, out, N, 1);
}

// round 8
// speedup vs baseline: 2.0583x; 1.1714x over previous
#include <cuda_runtime.h>
#include <cuda_fp16.h>
#include <cstdint>

#define D      128
#define TM     64
#define NMAX   50000
#define DEGMAX 128
#define EPS    1e-8f

#define ROWB  272           // bytes per fp16 tile row (136 halves)
#define SWF   132           // f32 staging stride

// ---------------- scratch (static device globals) ----------------
__device__ float g_y[NMAX * D];
__device__ int   g_hist[NMAX];              // in-degree (atomic counters)
__device__ int   g_csr[NMAX * DEGMAX];      // padded neighbor buckets
// transposed fp16 weights: [mat][n][k]; mat: 0=msg1,1=msg2,2=upd1,3=upd2
__device__ __half g_wt[4 * D * D];

// ---------------- smem layout (bytes) ----------------
#define OFF_AH 0u            /* 64 x 272  = 17408 */
#define OFF_AL 17408u
#define OFF_W1 34816u        /* 128 x 272 = 34816 */
#define OFF_W2 69632u
#define OFF_B1 104448u
#define OFF_B2 104960u
#define SMEM_DYN 105472u

// ---------------- PTX helpers ----------------
__device__ __forceinline__ uint32_t smem_u32(const void* p) {
    uint32_t a;
    asm("{ .reg .u64 t; cvta.to.shared.u64 t, %1; cvt.u32.u64 %0, t; }" : "=r"(a) : "l"(p));
    return a;
}
__device__ __forceinline__ void ldsm4(uint32_t* r, uint32_t addr) {
    asm volatile("ldmatrix.sync.aligned.m8n8.x4.shared.b16 {%0,%1,%2,%3}, [%4];"
        : "=r"(r[0]), "=r"(r[1]), "=r"(r[2]), "=r"(r[3]) : "r"(addr));
}
__device__ __forceinline__ void mma16816(float* c, const uint32_t* a,
                                         uint32_t b0, uint32_t b1) {
    asm("mma.sync.aligned.m16n8k16.row.col.f32.f16.f16.f32 "
        "{%0,%1,%2,%3}, {%4,%5,%6,%7}, {%8,%9}, {%0,%1,%2,%3};"
        : "+f"(c[0]), "+f"(c[1]), "+f"(c[2]), "+f"(c[3])
        : "r"(a[0]), "r"(a[1]), "r"(a[2]), "r"(a[3]), "r"(b0), "r"(b1));
}
__device__ __forceinline__ uint32_t packh2(__half a, __half b) {
    __half2 t = __halves2half2(a, b);
    return *(uint32_t*)&t;
}

// 2-term fp16 split GEMM (M64 tile): acc += (Ah+Al) @ W^T
// warp computes 32 rows (wm) x 32 cols (wn); frag loads via ldmatrix.x4
__device__ __forceinline__ void do_gemm(
    uint32_t sAH, uint32_t sAL, uint32_t sW,
    int wm, int wn, int lane, float acc[2][4][4])
{
    const uint32_t lrow = (uint32_t)(lane & 15) * ROWB + (uint32_t)(lane >> 4) * 16;
    const uint32_t aoff = (uint32_t)(wm * 32) * ROWB + lrow;
    const uint32_t woff = (uint32_t)(wn * 32) * ROWB + lrow;

    #pragma unroll
    for (int ks = 0; ks < 8; ks++) {
        const uint32_t kb = (uint32_t)ks * 32;
        uint32_t ah[2][4], al[2][4], wf[2][4];
        #pragma unroll
        for (int ms = 0; ms < 2; ms++) {
            ldsm4(ah[ms], sAH + aoff + ms * 16 * ROWB + kb);
            ldsm4(al[ms], sAL + aoff + ms * 16 * ROWB + kb);
        }
        #pragma unroll
        for (int np = 0; np < 2; np++)
            ldsm4(wf[np], sW + woff + np * 16 * ROWB + kb);
        // term 1: Ah * W  (8 independent chains)
        #pragma unroll
        for (int np = 0; np < 2; np++)
            #pragma unroll
            for (int h = 0; h < 2; h++)
                #pragma unroll
                for (int ms = 0; ms < 2; ms++)
                    mma16816(acc[ms][np * 2 + h], ah[ms], wf[np][h], wf[np][h + 2]);
        // term 2: Al * W
        #pragma unroll
        for (int np = 0; np < 2; np++)
            #pragma unroll
            for (int h = 0; h < 2; h++)
                #pragma unroll
                for (int ms = 0; ms < 2; ms++)
                    mma16816(acc[ms][np * 2 + h], al[ms], wf[np][h], wf[np][h + 2]);
    }
}

// ---------------- bucket-CSR build ----------------
__global__ void zero_hist_kernel(int n) {
    int i = blockIdx.x * blockDim.x + threadIdx.x;
    if (i < n) g_hist[i] = 0;
}
__global__ void fill_kernel(const int* __restrict__ ei, int E) {
    int e = blockIdx.x * blockDim.x + threadIdx.x;
    if (e < E) {
        int dst = ei[e];
        int src = ei[E + e];
        int pos = atomicAdd(&g_hist[dst], 1);
        if (pos < DEGMAX) g_csr[dst * DEGMAX + pos] = src;
    }
}

// transpose + fp16 convert of the 4 weight matrices
__global__ void prep_w_kernel(const float* __restrict__ w0, const float* __restrict__ w1,
                              const float* __restrict__ w2, const float* __restrict__ w3) {
    int g = blockIdx.x * blockDim.x + threadIdx.x;    // 0..16383
    int mat = g >> 12;
    int rem = g & 4095;
    int k = rem >> 5;
    int n4 = rem & 31;
    const float* W = (mat == 0) ? w0 : (mat == 1) ? w1 : (mat == 2) ? w2 : w3;
    float4 v = ((const float4*)W)[k * 32 + n4];
    float a[4] = {v.x, v.y, v.z, v.w};
    #pragma unroll
    for (int j = 0; j < 4; j++) {
        int n = n4 * 4 + j;
        g_wt[mat * D * D + n * D + k] = __float2half_rn(a[j]);
    }
}

__device__ __forceinline__ void f4add(float4& a, const float4 b) {
    a.x += b.x; a.y += b.y; a.z += b.z; a.w += b.w;
}

// ---------------- fused MLP via mma.sync (HMMA fp16), TM=64, 2 CTAs/SM ----------------
// mode 0: g_y = MLP1(logmap0(x))
// mode 1: out = expmap0(MLP2(mean_{bucket} g_y[src]))
__global__ __launch_bounds__(256, 2) void mlp_tc_kernel(
    const float* __restrict__ xin,
    const float* __restrict__ B1v, const float* __restrict__ B2v,
    float* __restrict__ outp, int N, int mode)
{
    extern __shared__ char sb[];
    const uint32_t sbase = smem_u32(sb);
    float* B1s = (float*)(sb + OFF_B1);
    float* B2s = (float*)(sb + OFF_B2);

    const int tid  = threadIdx.x;
    const int wid  = tid >> 5;
    const int lane = tid & 31;
    const int gid  = lane >> 2;
    const int tig  = lane & 3;
    const int wm   = wid & 1;          // 2 x M32
    const int wn   = wid >> 1;         // 4 x N32
    const int row0 = blockIdx.x * TM;

    if (tid < 128) B1s[tid] = B1v[tid];
    else           B2s[tid - 128] = B2v[tid - 128];

    // ---- load W1 AND W2 (fp16, both stay resident) into smem ----
    {
        int m1 = mode * 2, m2 = mode * 2 + 1;
        const float4* s1 = (const float4*)(g_wt + m1 * D * D);
        const float4* s2 = (const float4*)(g_wt + m2 * D * D);
        #pragma unroll
        for (int it = 0; it < 8; it++) {
            int idx = tid + it * 256;          // 2048 float4 per matrix
            int n = idx >> 4, c = idx & 15;
            *(float4*)(sb + OFF_W1 + n * ROWB + c * 16) = s1[idx];
            *(float4*)(sb + OFF_W2 + n * ROWB + c * 16) = s2[idx];
        }
    }

    // ---- input rows: logmap0(x) (mode 0) or bucket-gather mean (mode 1) ----
    {
        const float4* x4 = (const float4*)xin;
        const float4* y4 = (const float4*)g_y;
        #pragma unroll 2
        for (int i = 0; i < 8; i++) {
            int r = wid * 8 + i;
            int rg = row0 + r;
            float4 v = make_float4(0.f, 0.f, 0.f, 0.f);
            if (rg < N) {
                if (mode == 0) {
                    v = x4[rg * 32 + lane];
                    float ss = v.x * v.x + v.y * v.y + v.z * v.z + v.w * v.w;
                    #pragma unroll
                    for (int m = 16; m >= 1; m >>= 1) ss += __shfl_xor_sync(0xffffffffu, ss, m);
                    float nrm = sqrtf(ss);
                    float nc  = fminf(fmaxf(nrm, EPS), 1.0f - 1e-5f);
                    float f   = atanhf(nc) / nc;
                    v.x *= f; v.y *= f; v.z *= f; v.w *= f;
                } else {
                    const int* nb = g_csr + rg * DEGMAX;
                    int deg = g_hist[rg];
                    if (deg > DEGMAX) deg = DEGMAX;
                    float4 v1 = make_float4(0.f, 0.f, 0.f, 0.f);
                    float4 v2 = make_float4(0.f, 0.f, 0.f, 0.f);
                    float4 v3 = make_float4(0.f, 0.f, 0.f, 0.f);
                    int j = 0;
                    for (; j + 4 <= deg; j += 4) {
                        int s0 = nb[j], s1 = nb[j + 1], s2 = nb[j + 2], s3 = nb[j + 3];
                        f4add(v,  y4[s0 * 32 + lane]);
                        f4add(v1, y4[s1 * 32 + lane]);
                        f4add(v2, y4[s2 * 32 + lane]);
                        f4add(v3, y4[s3 * 32 + lane]);
                    }
                    for (; j < deg; j++)
                        f4add(v, y4[nb[j] * 32 + lane]);
                    f4add(v1, v2); f4add(v, v3); f4add(v, v1);
                    float inv = 1.0f / ((float)g_hist[rg] + EPS);
                    v.x *= inv; v.y *= inv; v.z *= inv; v.w *= inv;
                }
            }
            // fp16 hi/lo split of A
            __half h0 = __float2half_rn(v.x), h1 = __float2half_rn(v.y);
            __half h2 = __float2half_rn(v.z), h3 = __float2half_rn(v.w);
            __half l0 = __float2half_rn(v.x - __half2float(h0));
            __half l1 = __float2half_rn(v.y - __half2float(h1));
            __half l2 = __float2half_rn(v.z - __half2float(h2));
            __half l3 = __float2half_rn(v.w - __half2float(h3));
            *(uint2*)(sb + OFF_AH + r * ROWB + lane * 8) =
                make_uint2(packh2(h0, h1), packh2(h2, h3));
            *(uint2*)(sb + OFF_AL + r * ROWB + lane * 8) =
                make_uint2(packh2(l0, l1), packh2(l2, l3));
        }
    }
    __syncthreads();

    float acc[2][4][4];

    // ---- GEMM1 ----
    #pragma unroll
    for (int ms = 0; ms < 2; ms++)
        #pragma unroll
        for (int ns = 0; ns < 4; ns++)
            #pragma unroll
            for (int j = 0; j < 4; j++) acc[ms][ns][j] = 0.f;
    do_gemm(sbase + OFF_AH, sbase + OFF_AL, sbase + OFF_W1, wm, wn, lane, acc);
    __syncthreads();

    // ---- epilogue1: T = relu(acc + B1) -> Ah/Al (fp16 hi/lo) ----
    #pragma unroll
    for (int ms = 0; ms < 2; ms++) {
        int r = wm * 32 + ms * 16 + gid;
        #pragma unroll
        for (int ns = 0; ns < 4; ns++) {
            int col = wn * 32 + ns * 8 + tig * 2;
            float b0 = B1s[col], b1 = B1s[col + 1];
            float v0 = fmaxf(acc[ms][ns][0] + b0, 0.f);
            float v1 = fmaxf(acc[ms][ns][1] + b1, 0.f);
            float v2 = fmaxf(acc[ms][ns][2] + b0, 0.f);
            float v3 = fmaxf(acc[ms][ns][3] + b1, 0.f);
            __half a0 = __float2half_rn(v0), a1 = __float2half_rn(v1);
            __half a2 = __float2half_rn(v2), a3 = __float2half_rn(v3);
            __half c0 = __float2half_rn(v0 - __half2float(a0));
            __half c1 = __float2half_rn(v1 - __half2float(a1));
            __half c2 = __float2half_rn(v2 - __half2float(a2));
            __half c3 = __float2half_rn(v3 - __half2float(a3));
            *(uint32_t*)(sb + OFF_AH + r * ROWB + col * 2)       = packh2(a0, a1);
            *(uint32_t*)(sb + OFF_AL + r * ROWB + col * 2)       = packh2(c0, c1);
            *(uint32_t*)(sb + OFF_AH + (r + 8) * ROWB + col * 2) = packh2(a2, a3);
            *(uint32_t*)(sb + OFF_AL + (r + 8) * ROWB + col * 2) = packh2(c2, c3);
        }
    }
    __syncthreads();

    // ---- GEMM2 (W2 already resident — no reload phase) ----
    #pragma unroll
    for (int ms = 0; ms < 2; ms++)
        #pragma unroll
        for (int ns = 0; ns < 4; ns++)
            #pragma unroll
            for (int j = 0; j < 4; j++) acc[ms][ns][j] = 0.f;
    do_gemm(sbase + OFF_AH, sbase + OFF_AL, sbase + OFF_W2, wm, wn, lane, acc);

    if (mode == 0) {
        #pragma unroll
        for (int ms = 0; ms < 2; ms++) {
            int r = wm * 32 + ms * 16 + gid;
            #pragma unroll
            for (int ns = 0; ns < 4; ns++) {
                int col = wn * 32 + ns * 8 + tig * 2;
                float b0 = B2s[col], b1 = B2s[col + 1];
                int rg = row0 + r;
                if (rg < N)
                    *(float2*)(g_y + rg * D + col) =
                        make_float2(acc[ms][ns][0] + b0, acc[ms][ns][1] + b1);
                if (rg + 8 < N)
                    *(float2*)(g_y + (rg + 8) * D + col) =
                        make_float2(acc[ms][ns][2] + b0, acc[ms][ns][3] + b1);
            }
        }
    } else {
        __syncthreads();
        float* Sf = (float*)(sb + OFF_W1);        // reuse W1 region: 64 x 132 f32 staging
        #pragma unroll
        for (int ms = 0; ms < 2; ms++) {
            int r = wm * 32 + ms * 16 + gid;
            #pragma unroll
            for (int ns = 0; ns < 4; ns++) {
                int col = wn * 32 + ns * 8 + tig * 2;
                float b0 = B2s[col], b1 = B2s[col + 1];
                *(float2*)(Sf + r * SWF + col) =
                    make_float2(acc[ms][ns][0] + b0, acc[ms][ns][1] + b1);
                *(float2*)(Sf + (r + 8) * SWF + col) =
                    make_float2(acc[ms][ns][2] + b0, acc[ms][ns][3] + b1);
            }
        }
        __syncthreads();
        // expmap0: 4 threads per row
        int r = tid >> 2, q = tid & 3;
        float ss = 0.f;
        float4 vv[8];
        #pragma unroll
        for (int j = 0; j < 8; j++) {
            float4 v = *(float4*)(Sf + r * SWF + q * 32 + j * 4);
            vv[j] = v;
            ss += v.x * v.x + v.y * v.y + v.z * v.z + v.w * v.w;
        }
        ss += __shfl_xor_sync(0xffffffffu, ss, 1);
        ss += __shfl_xor_sync(0xffffffffu, ss, 2);
        float nrm = sqrtf(ss);
        float nc  = fmaxf(nrm, EPS);
        float fm  = tanhf(nc) / nc;
        int rg = row0 + r;
        if (rg < N) {
            #pragma unroll
            for (int j = 0; j < 8; j++) {
                float4 v = vv[j];
                v.x *= fm; v.y *= fm; v.z *= fm; v.w *= fm;
                ((float4*)outp)[rg * 32 + q * 8 + j] = v;
            }
        }
    }
}

// ---------------- launch ----------------
extern "C" void kernel_launch(void* const* d_in, const int* in_sizes, int n_in,
                              void* d_out, int out_size) {
    const float* x      = (const float*)d_in[0];
    const int*   ei     = (const int*)d_in[1];
    const float* w_msg1 = (const float*)d_in[2];
    const float* b_msg1 = (const float*)d_in[3];
    const float* w_msg2 = (const float*)d_in[4];
    const float* b_msg2 = (const float*)d_in[5];
    const float* w_upd1 = (const float*)d_in[6];
    const float* b_upd1 = (const float*)d_in[7];
    const float* w_upd2 = (const float*)d_in[8];
    const float* b_upd2 = (const float*)d_in[9];
    float* out = (float*)d_out;

    int N = in_sizes[0] / D;
    int E = in_sizes[1] / 2;

    cudaFuncSetAttribute(mlp_tc_kernel,
                         cudaFuncAttributeMaxDynamicSharedMemorySize, SMEM_DYN);

    prep_w_kernel<<<64, 256>>>(w_msg1, w_msg2, w_upd1, w_upd2);
    zero_hist_kernel<<<(N + 255) / 256, 256>>>(N);
    fill_kernel<<<(E + 255) / 256, 256>>>(ei, E);

    int mblocks = (N + TM - 1) / TM;
    mlp_tc_kernel<<<mblocks, 256, SMEM_DYN>>>(x, b_msg1, b_msg2, nullptr, N, 0);
    mlp_tc_kernel<<<mblocks, 256, SMEM_DYN>>>(nullptr, b_upd1, b_upd2, out, N, 1);
}